// round 1
// baseline (speedup 1.0000x reference)
#include <cuda_runtime.h>
#include <math.h>
#include <stdint.h>

#define HIDDEN 2048
#define NH 16
#define HD 128
#define BATCH 2
#define SEQ 2048
#define MROWS (BATCH*SEQ)

// Scratch (device globals — no allocation allowed)
__device__ float g_q[(size_t)BATCH*NH*SEQ*HD];     // (b,h,s,d)
__device__ float g_k[(size_t)BATCH*NH*SEQ*HD];     // (b,h,s,d)
__device__ float g_v[(size_t)BATCH*NH*SEQ*HD];     // (b,h,s,d)
__device__ float g_attn[(size_t)BATCH*SEQ*NH*HD];  // (b,s,h,d) == [4096,2048] row-major

// ---------------------------------------------------------------------------
// SGEMM: C[M=4096, N=2048] = A[4096, 2048] * W[2048, 2048]
// MODE 0: row-major store to out[M,N]
// MODE 1: scatter to (b, h, s, d) layout for Q/K/V
// ---------------------------------------------------------------------------
template<int MODE>
__global__ __launch_bounds__(256) void gemm_kernel(
    const float* __restrict__ A, const float* __restrict__ W, float* __restrict__ out)
{
    const int N = 2048, K = 2048;
    __shared__ float As[8][128];
    __shared__ float Bs[8][128];

    const int tid = threadIdx.x;
    const int tx = tid & 15, ty = tid >> 4;
    const int rowBase = blockIdx.y * 128;
    const int colBase = blockIdx.x * 128;

    // A tile loaders: 128 rows x 8 k -> one float4 per thread
    const int ar = tid >> 1, ak = (tid & 1) << 2;
    // B tile loaders: 8 rows x 128 cols -> one float4 per thread
    const int bk = tid >> 5, bc = (tid & 31) << 2;

    const float* Ap = A + (size_t)(rowBase + ar) * K + ak;
    const float* Wp = W + (size_t)bk * N + colBase + bc;

    float acc[8][8];
#pragma unroll
    for (int i = 0; i < 8; i++)
#pragma unroll
        for (int j = 0; j < 8; j++) acc[i][j] = 0.f;

    for (int k0 = 0; k0 < K; k0 += 8) {
        float4 a4 = *(const float4*)(Ap + k0);
        float4 b4 = *(const float4*)(Wp + (size_t)k0 * N);
        As[ak + 0][ar] = a4.x;
        As[ak + 1][ar] = a4.y;
        As[ak + 2][ar] = a4.z;
        As[ak + 3][ar] = a4.w;
        *(float4*)&Bs[bk][bc] = b4;
        __syncthreads();
#pragma unroll
        for (int kk = 0; kk < 8; kk++) {
            float ra[8], rb[8];
#pragma unroll
            for (int i = 0; i < 8; i++) ra[i] = As[kk][ty + 16 * i];
#pragma unroll
            for (int j = 0; j < 8; j++) rb[j] = Bs[kk][tx + 16 * j];
#pragma unroll
            for (int i = 0; i < 8; i++)
#pragma unroll
                for (int j = 0; j < 8; j++)
                    acc[i][j] = fmaf(ra[i], rb[j], acc[i][j]);
        }
        __syncthreads();
    }

#pragma unroll
    for (int i = 0; i < 8; i++) {
        int r = rowBase + ty + 16 * i;
#pragma unroll
        for (int j = 0; j < 8; j++) {
            int c = colBase + tx + 16 * j;
            if (MODE == 0) {
                out[(size_t)r * N + c] = acc[i][j];
            } else {
                int b = r >> 11, s = r & (SEQ - 1);
                int h = c >> 7, d = c & (HD - 1);
                out[(((size_t)b * NH + h) * SEQ + s) * HD + d] = acc[i][j];
            }
        }
    }
}

// ---------------------------------------------------------------------------
// RoPE (in place on (b,h,s,d) tensor). Mimics reference fp32 rounding:
// inv_freq = 1/powf(10000, 2j/128) in f32; angle = pos * inv in f32; precise sincos.
// Block: 256 threads = 4 rows x 64 lane-pairs. Grid: (SEQ/4, BATCH*NH)
// ---------------------------------------------------------------------------
__global__ __launch_bounds__(256) void rope_kernel(float* __restrict__ ten,
                                                   const int* __restrict__ pos_ids)
{
    int lane = threadIdx.x & 63;
    int rsub = threadIdx.x >> 6;
    int s = blockIdx.x * 4 + rsub;
    int bh = blockIdx.y;
    int pos = pos_ids[s];

    float t = powf(10000.0f, (float)(2 * lane) * (1.0f / 128.0f));
    float inv = 1.0f / t;
    float ang = (float)pos * inv;
    float sn, cs;
    sincosf(ang, &sn, &cs);

    float* p = ten + ((size_t)bh * SEQ + s) * HD;
    float x1 = p[lane];
    float x2 = p[lane + 64];
    p[lane]      = x1 * cs - x2 * sn;
    p[lane + 64] = x2 * cs + x1 * sn;
}

// ---------------------------------------------------------------------------
// Flash attention fp32, non-causal. BQ=64 query rows per block, BKV=64.
// Grid: (SEQ/64, BATCH*NH). 256 threads: thread (ty,tx)=(tid>>4, tid&15)
// owns S rows {ty+16i}, S cols {tx+16j}, O cols {tx+16j, j<8}.
// Dynamic smem: qs[128][68] (Q^T), kvs (K^T 128x68 / V 64x132), ps[64][66].
// ---------------------------------------------------------------------------
#define QS_STRIDE 68
#define VS_STRIDE 132
#define PS_STRIDE 66
#define ATTN_SMEM_FLOATS (128*QS_STRIDE + 128*QS_STRIDE + 64*PS_STRIDE)

__global__ __launch_bounds__(256, 2) void attn_kernel(
    const float* __restrict__ Q, const float* __restrict__ K,
    const float* __restrict__ V, float* __restrict__ Out)
{
    extern __shared__ float smem[];
    float* qs  = smem;                       // [d*68 + r], Q transposed
    float* kvs = smem + 128 * QS_STRIDE;     // K: [d*68 + c] ; V: [kv*132 + d]
    float* ps  = kvs + 128 * QS_STRIDE;      // [r*66 + c]

    const int tid = threadIdx.x;
    const int tx = tid & 15, ty = tid >> 4;
    const int qt = blockIdx.x;   // query tile 0..31
    const int bh = blockIdx.y;   // b*NH + h

    const float* Qb = Q + ((size_t)bh * SEQ + qt * 64) * HD;
    const float* Kb = K + (size_t)bh * SEQ * HD;
    const float* Vb = V + (size_t)bh * SEQ * HD;

    // Load Q tile transposed: conflict-free stores (lanes write consecutive r)
    {
        int r = tid & 63;
        int g0 = tid >> 6;
#pragma unroll
        for (int it = 0; it < 8; it++) {
            int dg = g0 + 4 * it;    // float4 index along d
            float4 v4 = *(const float4*)(Qb + (size_t)r * HD + dg * 4);
            qs[(dg * 4 + 0) * QS_STRIDE + r] = v4.x;
            qs[(dg * 4 + 1) * QS_STRIDE + r] = v4.y;
            qs[(dg * 4 + 2) * QS_STRIDE + r] = v4.z;
            qs[(dg * 4 + 3) * QS_STRIDE + r] = v4.w;
        }
    }

    float m[4], l[4], o[4][8];
#pragma unroll
    for (int i = 0; i < 4; i++) {
        m[i] = -1e30f; l[i] = 0.f;
#pragma unroll
        for (int j = 0; j < 8; j++) o[i][j] = 0.f;
    }

    const float SCALE = 0.08838834764831845f;  // 1/sqrt(128)
    const unsigned FULL = 0xffffffffu;

    __syncthreads();

    for (int t = 0; t < SEQ / 64; t++) {
        // Load K tile transposed into kvs
        {
            int r = tid & 63;
            int g0 = tid >> 6;
            const float* Kt = Kb + (size_t)t * 64 * HD;
#pragma unroll
            for (int it = 0; it < 8; it++) {
                int dg = g0 + 4 * it;
                float4 v4 = *(const float4*)(Kt + (size_t)r * HD + dg * 4);
                kvs[(dg * 4 + 0) * QS_STRIDE + r] = v4.x;
                kvs[(dg * 4 + 1) * QS_STRIDE + r] = v4.y;
                kvs[(dg * 4 + 2) * QS_STRIDE + r] = v4.z;
                kvs[(dg * 4 + 3) * QS_STRIDE + r] = v4.w;
            }
        }
        __syncthreads();

        // S = Q K^T (raw dots)
        float sc[4][4];
#pragma unroll
        for (int i = 0; i < 4; i++)
#pragma unroll
            for (int j = 0; j < 4; j++) sc[i][j] = 0.f;

#pragma unroll 8
        for (int k = 0; k < 128; k++) {
            float ra[4], rb[4];
#pragma unroll
            for (int i = 0; i < 4; i++) ra[i] = qs[k * QS_STRIDE + ty + 16 * i];
#pragma unroll
            for (int j = 0; j < 4; j++) rb[j] = kvs[k * QS_STRIDE + tx + 16 * j];
#pragma unroll
            for (int i = 0; i < 4; i++)
#pragma unroll
                for (int j = 0; j < 4; j++)
                    sc[i][j] = fmaf(ra[i], rb[j], sc[i][j]);
        }
        __syncthreads();   // done reading K from kvs

        // Load V tile (natural layout) into kvs — overlaps with softmax below
        {
            const float* Vt = Vb + (size_t)t * 64 * HD;
#pragma unroll
            for (int it = 0; it < 8; it++) {
                int i4 = tid + 256 * it;
                int kv = i4 >> 5, dg = i4 & 31;
                float4 v4 = *(const float4*)(Vt + (size_t)kv * HD + dg * 4);
                *(float4*)&kvs[kv * VS_STRIDE + dg * 4] = v4;
            }
        }

        // Online softmax: row reductions over the 16 tx lanes (xor 1,2,4,8)
#pragma unroll
        for (int i = 0; i < 4; i++) {
            float mx = fmaxf(fmaxf(sc[i][0], sc[i][1]), fmaxf(sc[i][2], sc[i][3]));
            mx = fmaxf(mx, __shfl_xor_sync(FULL, mx, 1));
            mx = fmaxf(mx, __shfl_xor_sync(FULL, mx, 2));
            mx = fmaxf(mx, __shfl_xor_sync(FULL, mx, 4));
            mx = fmaxf(mx, __shfl_xor_sync(FULL, mx, 8));
            mx *= SCALE;
            float mn = fmaxf(m[i], mx);
            float corr = __expf(m[i] - mn);
            m[i] = mn;
            float rs = 0.f;
#pragma unroll
            for (int j = 0; j < 4; j++) {
                float p = __expf(fmaf(sc[i][j], SCALE, -mn));
                ps[(ty + 16 * i) * PS_STRIDE + tx + 16 * j] = p;
                rs += p;
            }
            rs += __shfl_xor_sync(FULL, rs, 1);
            rs += __shfl_xor_sync(FULL, rs, 2);
            rs += __shfl_xor_sync(FULL, rs, 4);
            rs += __shfl_xor_sync(FULL, rs, 8);
            l[i] = l[i] * corr + rs;
#pragma unroll
            for (int j = 0; j < 8; j++) o[i][j] *= corr;
        }
        __syncthreads();   // V + P ready

        // O += P * V
#pragma unroll 4
        for (int kk = 0; kk < 64; kk++) {
            float pa[4], vb[8];
#pragma unroll
            for (int i = 0; i < 4; i++) pa[i] = ps[(ty + 16 * i) * PS_STRIDE + kk];
#pragma unroll
            for (int j = 0; j < 8; j++) vb[j] = kvs[kk * VS_STRIDE + tx + 16 * j];
#pragma unroll
            for (int i = 0; i < 4; i++)
#pragma unroll
                for (int j = 0; j < 8; j++)
                    o[i][j] = fmaf(pa[i], vb[j], o[i][j]);
        }
        __syncthreads();   // done reading V/P before next tile overwrites
    }

    // Normalize and write to (b, s, h, d)
    int b = bh >> 4, h = bh & 15;
#pragma unroll
    for (int i = 0; i < 4; i++) {
        int s = qt * 64 + ty + 16 * i;
        float inv_l = 1.0f / l[i];
#pragma unroll
        for (int j = 0; j < 8; j++) {
            int d = tx + 16 * j;
            Out[(((size_t)b * SEQ + s) * NH + h) * HD + d] = o[i][j] * inv_l;
        }
    }
}

// ---------------------------------------------------------------------------
extern "C" void kernel_launch(void* const* d_in, const int* in_sizes, int n_in,
                              void* d_out, int out_size)
{
    const float* hidden = (const float*)d_in[0];
    const int*   posids = (const int*)d_in[1];
    const float* wq     = (const float*)d_in[2];
    const float* wk     = (const float*)d_in[3];
    const float* wv     = (const float*)d_in[4];
    const float* wo     = (const float*)d_in[5];
    float* out = (float*)d_out;

    float *q, *k, *v, *attn;
    cudaGetSymbolAddress((void**)&q, g_q);
    cudaGetSymbolAddress((void**)&k, g_k);
    cudaGetSymbolAddress((void**)&v, g_v);
    cudaGetSymbolAddress((void**)&attn, g_attn);

    const size_t attn_smem = (size_t)ATTN_SMEM_FLOATS * sizeof(float);
    cudaFuncSetAttribute(attn_kernel, cudaFuncAttributeMaxDynamicSharedMemorySize,
                         (int)attn_smem);

    dim3 gemm_grid(2048 / 128, MROWS / 128);   // (16, 32)

    // QKV projections (scatter epilogue into (b,h,s,d))
    gemm_kernel<1><<<gemm_grid, 256>>>(hidden, wq, q);
    gemm_kernel<1><<<gemm_grid, 256>>>(hidden, wk, k);
    gemm_kernel<1><<<gemm_grid, 256>>>(hidden, wv, v);

    // RoPE on Q and K
    dim3 rope_grid(SEQ / 4, BATCH * NH);
    rope_kernel<<<rope_grid, 256>>>(q, posids);
    rope_kernel<<<rope_grid, 256>>>(k, posids);

    // Attention
    dim3 attn_grid(SEQ / 64, BATCH * NH);      // (32, 32)
    attn_kernel<<<attn_grid, 256, attn_smem>>>(q, k, v, attn);

    // Output projection straight into d_out
    gemm_kernel<0><<<gemm_grid, 256>>>(attn, wo, out);
}